// round 5
// baseline (speedup 1.0000x reference)
#include <cuda_runtime.h>
#include <cuda_bf16.h>
#include <cstdint>

// ============================================================================
// QuantizedActorMLP on mma.sync (bf16 HMMA, sm_80+ path — tcgen05 is not
// available through this toolchain's ptxas target).
// x[B,17] -> fq -> L1(17->64)+fq -> L2(64->64)+fq -> L3(64->6).
// All dot products are exact integer math carried in bf16-in / f32-acc MMAs.
// Register chain: C-fragment of layer N == A-fragment of layer N+1.
// ============================================================================

#define ACT_SCALE 1.33f
#define QMAXF     127.0f
#define MAGIC     12582912.0f   // 1.5 * 2^23 : RNE round-to-int via add/sub

// ---- per-layer scalar constants ----
struct QConst { float G1, G2, G3; };
__device__   QConst gQ;
__constant__ QConst cQ;

// ---- weights pre-baked in m16n8k16 B-fragment order ----
// chunk layout: u32[chunk][lane][4], one LDS.128 per (lane, chunk).
__device__ uint32_t gW1f[8 * 128];    // L1: kt(2) x ntp(4) chunks
__device__ uint32_t gW2f[16 * 128];   // L2: kt(4) x ntp(4)
__device__ uint32_t gW3f[2 * 128];    // L3: ktp(2), j = kt%2*2+jj
__device__ float    gB1s[64];         // b1/step
__device__ float    gB2s[64];         // b2/step
__device__ float    gB3[8];           // b3 (cols 6,7 = 0)

// ---- helpers ----
// bf16x2 pack: res = {lo = vlo, hi = vhi}
#define CVT_BF16X2(res, vlo, vhi) \
    asm("cvt.rn.bf16x2.f32 %0, %1, %2;" : "=r"(res) : "f"(vhi), "f"(vlo))

#define MMA16816(Cv, Av, b0, b1)                                              \
    asm volatile(                                                             \
        "mma.sync.aligned.m16n8k16.row.col.f32.bf16.bf16.f32 "                \
        "{%0,%1,%2,%3}, {%4,%5,%6,%7}, {%8,%9}, {%0,%1,%2,%3};"               \
        : "+f"((Cv)[0]), "+f"((Cv)[1]), "+f"((Cv)[2]), "+f"((Cv)[3])          \
        : "r"((Av)[0]), "r"((Av)[1]), "r"((Av)[2]), "r"((Av)[3]),             \
          "r"(b0), "r"(b1))

// quantize one float to an integer-valued float (clamp +-scale, RNE round)
__device__ __forceinline__ float quant_in(float v) {
    const float INV = QMAXF / ACT_SCALE;
    v = fminf(fmaxf(v, -ACT_SCALE), ACT_SCALE);
    float t = fmaf(v, INV, MAGIC);
    return __fadd_rn(t, -MAGIC);
}

// requant 2 accumulators -> packed int-valued bf16x2
__device__ __forceinline__ uint32_t requant2(float c0, float c1, float G, float2 b) {
    float f0 = fmaf(c0, G, b.x);
    float f1 = fmaf(c1, G, b.y);
    f0 = fminf(fmaxf(f0, -QMAXF), QMAXF);
    f1 = fminf(fmaxf(f1, -QMAXF), QMAXF);
    f0 = __fadd_rn(__fadd_rn(f0, MAGIC), -MAGIC);
    f1 = __fadd_rn(__fadd_rn(f1, MAGIC), -MAGIC);
    uint32_t r; CVT_BF16X2(r, f0, f1);
    return r;
}

// quantize one weight to int-valued bf16 bits
__device__ __forceinline__ uint16_t qweight(float w, float s) {
    float r = rintf(w / s);
    r = fminf(fmaxf(r, -QMAXF), QMAXF);
    return __bfloat16_as_ushort(__float2bfloat16(r));
}

// ============================================================================
// Prep: scales, quantize weights, bake into B-fragment order.
// Fragment convention (m16n8k16, row.col):
//   B reg b0 of tile (kt, nt), lane L: n = nt*8 + L/4, k0 = kt*16 + (L%4)*2,
//      b0 = bf16x2{ lo = W[n][k0], hi = W[n][k0+1] },  b1: k0+8.
// ============================================================================
__global__ void prep_kernel(const float* __restrict__ W1, const float* __restrict__ b1,
                            const float* __restrict__ W2, const float* __restrict__ b2,
                            const float* __restrict__ W3, const float* __restrict__ b3) {
    __shared__ float red[256];
    __shared__ float sS[3];
    const int tid = threadIdx.x;
    const float* Ws[3]  = {W1, W2, W3};
    const int    nel[3] = {64 * 17, 64 * 64, 6 * 64};

    for (int t = 0; t < 3; ++t) {
        float m = 0.0f;
        for (int i = tid; i < nel[t]; i += 256) m = fmaxf(m, fabsf(Ws[t][i]));
        red[tid] = m; __syncthreads();
        for (int s = 128; s > 0; s >>= 1) {
            if (tid < s) red[tid] = fmaxf(red[tid], red[tid + s]);
            __syncthreads();
        }
        if (tid == 0) sS[t] = red[0] / QMAXF;
        __syncthreads();
    }
    const float s1 = sS[0], s2 = sS[1], s3 = sS[2];
    const float step = ACT_SCALE / QMAXF;
    if (tid == 0) { gQ.G1 = s1; gQ.G2 = s2; gQ.G3 = step * s3; }
    if (tid < 64) { gB1s[tid] = b1[tid] / step; gB2s[tid] = b2[tid] / step; }
    if (tid < 8)  gB3[tid] = (tid < 6) ? b3[tid] : 0.0f;

    // L1 frags: chunks c = kt*4 + ntp, j in 0..3: nt = ntp*2 + j/2, jj = j%2
    for (int idx = tid; idx < 8 * 128; idx += 256) {
        int c = idx >> 7, rem = idx & 127;
        int lane = rem >> 2, j = rem & 3;
        int kt = c >> 2, ntp = c & 3;
        int nt = ntp * 2 + (j >> 1), jj = j & 1;
        int n  = nt * 8 + (lane >> 2);
        int k0 = kt * 16 + (lane & 3) * 2 + jj * 8;
        uint16_t lo = (k0     < 17) ? qweight(W1[n * 17 + k0],     s1) : (uint16_t)0;
        uint16_t hi = (k0 + 1 < 17) ? qweight(W1[n * 17 + k0 + 1], s1) : (uint16_t)0;
        gW1f[idx] = (uint32_t)lo | ((uint32_t)hi << 16);
    }
    // L2 frags
    for (int idx = tid; idx < 16 * 128; idx += 256) {
        int c = idx >> 7, rem = idx & 127;
        int lane = rem >> 2, j = rem & 3;
        int kt = c >> 2, ntp = c & 3;
        int nt = ntp * 2 + (j >> 1), jj = j & 1;
        int n  = nt * 8 + (lane >> 2);
        int k0 = kt * 16 + (lane & 3) * 2 + jj * 8;
        uint16_t lo = qweight(W2[(n << 6) + k0],     s2);
        uint16_t hi = qweight(W2[(n << 6) + k0 + 1], s2);
        gW2f[idx] = (uint32_t)lo | ((uint32_t)hi << 16);
    }
    // L3 frags: chunks c = ktp, j: kt = ktp*2 + j/2, jj = j%2, single N-tile
    for (int idx = tid; idx < 2 * 128; idx += 256) {
        int c = idx >> 7, rem = idx & 127;
        int lane = rem >> 2, j = rem & 3;
        int kt = c * 2 + (j >> 1), jj = j & 1;
        int n  = lane >> 2;
        int k0 = kt * 16 + (lane & 3) * 2 + jj * 8;
        uint16_t lo = (n < 6) ? qweight(W3[(n << 6) + k0],     s3) : (uint16_t)0;
        uint16_t hi = (n < 6) ? qweight(W3[(n << 6) + k0 + 1], s3) : (uint16_t)0;
        gW3f[idx] = (uint32_t)lo | ((uint32_t)hi << 16);
    }
}

// ============================================================================
// Main kernel: 256 threads = 8 warps, each warp owns one 16-row m-tile
// (128 rows / CTA). Full register chain between layers.
// ============================================================================
__global__ __launch_bounds__(256, 2) void mlp_kernel(
    const float* __restrict__ x, float* __restrict__ out, int B) {

    __shared__ float    sx[128 * 18];          // padded stride 18
    __shared__ uint32_t sW1[8 * 128];
    __shared__ uint32_t sW2[16 * 128];
    __shared__ uint32_t sW3[2 * 128];
    __shared__ float    sb1[64], sb2[64], sb3[8];

    const int tid  = threadIdx.x;
    const int warp = tid >> 5;
    const int lane = tid & 31;
    const int g    = lane >> 2;   // row group 0..7
    const int t    = lane & 3;    // col/k group 0..3
    const int rowbase = blockIdx.x * 128;

    // ---- stage weights + biases + input tile ----
    for (int i = tid; i < 8 * 128;  i += 256) sW1[i] = gW1f[i];
    for (int i = tid; i < 16 * 128; i += 256) sW2[i] = gW2f[i];
    sW3[tid] = gW3f[tid];
    if (tid < 64) { sb1[tid] = gB1s[tid]; sb2[tid] = gB2s[tid]; }
    if (tid < 8)  sb3[tid] = gB3[tid];

    for (int i = tid; i < 128 * 17; i += 256) {
        int r = i / 17, k = i - r * 17;
        int gr = rowbase + r;
        sx[r * 18 + k] = (gr < B) ? x[(size_t)gr * 17 + k] : 0.0f;
    }
    __syncthreads();

    const int r0 = warp * 16 + g;     // local rows
    const int r1 = r0 + 8;

    // ---- input A fragments (K = 32, cols >= 17 zero) ----
    uint32_t A1[2][4];
    {
        const float* x0 = sx + r0 * 18;
        const float* x1 = sx + r1 * 18;
        float q00 = quant_in(x0[2 * t]),      q01 = quant_in(x0[2 * t + 1]);
        float q10 = quant_in(x1[2 * t]),      q11 = quant_in(x1[2 * t + 1]);
        float q02 = quant_in(x0[2 * t + 8]),  q03 = quant_in(x0[2 * t + 9]);
        float q12 = quant_in(x1[2 * t + 8]),  q13 = quant_in(x1[2 * t + 9]);
        CVT_BF16X2(A1[0][0], q00, q01);
        CVT_BF16X2(A1[0][1], q10, q11);
        CVT_BF16X2(A1[0][2], q02, q03);
        CVT_BF16X2(A1[0][3], q12, q13);
        if (t == 0) {
            float q16a = quant_in(x0[16]);
            float q16b = quant_in(x1[16]);
            CVT_BF16X2(A1[1][0], q16a, 0.0f);
            CVT_BF16X2(A1[1][1], q16b, 0.0f);
        } else {
            A1[1][0] = 0u; A1[1][1] = 0u;
        }
        A1[1][2] = 0u; A1[1][3] = 0u;
    }

    const float G1 = cQ.G1, G2 = cQ.G2, G3 = cQ.G3;
    const float2* sb1v = (const float2*)sb1;   // pair index nt*4 + t
    const float2* sb2v = (const float2*)sb2;

    // ---- layer 1 MMAs: kt 0..1, 8 N-tiles ----
    float C[8][4];
#pragma unroll
    for (int nt = 0; nt < 8; ++nt)
#pragma unroll
        for (int j = 0; j < 4; ++j) C[nt][j] = 0.0f;
#pragma unroll
    for (int kt = 0; kt < 2; ++kt) {
#pragma unroll
        for (int p = 0; p < 4; ++p) {
            uint4 w = *(const uint4*)&sW1[((kt * 4 + p) << 7) + (lane << 2)];
            MMA16816(C[2 * p],     A1[kt], w.x, w.y);
            MMA16816(C[2 * p + 1], A1[kt], w.z, w.w);
        }
    }

    // ---- requant 1 -> A2 (C frag == next A frag) ----
    uint32_t A2[4][4];
#pragma unroll
    for (int kt = 0; kt < 4; ++kt) {
        float2 bA = sb1v[(2 * kt) * 4 + t];
        float2 bB = sb1v[(2 * kt + 1) * 4 + t];
        A2[kt][0] = requant2(C[2 * kt][0],     C[2 * kt][1],     G1, bA);
        A2[kt][1] = requant2(C[2 * kt][2],     C[2 * kt][3],     G1, bA);
        A2[kt][2] = requant2(C[2 * kt + 1][0], C[2 * kt + 1][1], G1, bB);
        A2[kt][3] = requant2(C[2 * kt + 1][2], C[2 * kt + 1][3], G1, bB);
    }

    // ---- layer 2 MMAs: kt 0..3, 8 N-tiles ----
#pragma unroll
    for (int nt = 0; nt < 8; ++nt)
#pragma unroll
        for (int j = 0; j < 4; ++j) C[nt][j] = 0.0f;
#pragma unroll
    for (int kt = 0; kt < 4; ++kt) {
#pragma unroll
        for (int p = 0; p < 4; ++p) {
            uint4 w = *(const uint4*)&sW2[((kt * 4 + p) << 7) + (lane << 2)];
            MMA16816(C[2 * p],     A2[kt], w.x, w.y);
            MMA16816(C[2 * p + 1], A2[kt], w.z, w.w);
        }
    }

    // ---- requant 2 -> A3 ----
    uint32_t A3[4][4];
#pragma unroll
    for (int kt = 0; kt < 4; ++kt) {
        float2 bA = sb2v[(2 * kt) * 4 + t];
        float2 bB = sb2v[(2 * kt + 1) * 4 + t];
        A3[kt][0] = requant2(C[2 * kt][0],     C[2 * kt][1],     G2, bA);
        A3[kt][1] = requant2(C[2 * kt][2],     C[2 * kt][3],     G2, bA);
        A3[kt][2] = requant2(C[2 * kt + 1][0], C[2 * kt + 1][1], G2, bB);
        A3[kt][3] = requant2(C[2 * kt + 1][2], C[2 * kt + 1][3], G2, bB);
    }

    // ---- layer 3: single N-tile (6 real cols), kt 0..3 ----
    float D[4] = {0.0f, 0.0f, 0.0f, 0.0f};
#pragma unroll
    for (int p = 0; p < 2; ++p) {
        uint4 w = *(const uint4*)&sW3[(p << 7) + (lane << 2)];
        MMA16816(D, A3[2 * p],     w.x, w.y);
        MMA16816(D, A3[2 * p + 1], w.z, w.w);
    }

    // ---- epilogue: out[row, 2t..2t+1] (t < 3) ----
    if (t < 3) {
        const float2 b3p = *(const float2*)&sb3[2 * t];
        const int gr0 = rowbase + r0;
        const int gr1 = rowbase + r1;
        if (gr0 < B) {
            float2 o;
            o.x = fmaf(D[0], G3, b3p.x);
            o.y = fmaf(D[1], G3, b3p.y);
            *(float2*)&out[(size_t)gr0 * 6 + 2 * t] = o;
        }
        if (gr1 < B) {
            float2 o;
            o.x = fmaf(D[2], G3, b3p.x);
            o.y = fmaf(D[3], G3, b3p.y);
            *(float2*)&out[(size_t)gr1 * 6 + 2 * t] = o;
        }
    }
}

extern "C" void kernel_launch(void* const* d_in, const int* in_sizes, int n_in,
                              void* d_out, int out_size) {
    const float* x  = (const float*)d_in[0];
    const float* W1 = (const float*)d_in[1];
    const float* b1 = (const float*)d_in[2];
    const float* W2 = (const float*)d_in[3];
    const float* b2 = (const float*)d_in[4];
    const float* W3 = (const float*)d_in[5];
    const float* b3 = (const float*)d_in[6];
    float* out = (float*)d_out;

    const int B = in_sizes[0] / 17;
    const int blocks = (B + 127) / 128;

    prep_kernel<<<1, 256>>>(W1, b1, W2, b2, W3, b3);

    void* gq_ptr = nullptr;
    cudaGetSymbolAddress(&gq_ptr, gQ);
    cudaMemcpyToSymbolAsync(cQ, gq_ptr, sizeof(QConst), 0,
                            cudaMemcpyDeviceToDevice, 0);

    mlp_kernel<<<blocks, 256>>>(x, out, B);
}

// round 7
// speedup vs baseline: 1.1139x; 1.1139x over previous
#include <cuda_runtime.h>
#include <cuda_bf16.h>
#include <cstdint>

// ============================================================================
// QuantizedActorMLP on mma.sync bf16 HMMA.
// x[B,17] -> fq -> L1(17->64)+fq -> L2(64->64)+fq -> L3(64->6).
// Exact integer math carried in bf16-in / f32-acc MMAs.
// Register chain: C-fragment of layer N == A-fragment of layer N+1.
// Round 7: Round 6 structure (2 M-tiles/warp, per-pair requant) with the
// Round-5-proven requant sequence (NO magic-space bias fold — pre-adding
// MAGIC to b/step pre-rounds the bias and corrupts results).
// ============================================================================

#define ACT_SCALE 1.33f
#define QMAXF     127.0f
#define MAGIC     12582912.0f      // 1.5 * 2^23 : RNE integer round via add/sub

// ---- per-layer scalar constants ----
struct QConst { float G1, G2, G3; };
__device__   QConst gQ;
__constant__ QConst cQ;

// ---- weights pre-baked in m16n8k16 B-fragment order ----
__device__ uint32_t gW1f[8 * 128];    // L1: kt(2) x ntp(4) chunks
__device__ uint32_t gW2f[16 * 128];   // L2: kt(4) x ntp(4)
__device__ uint32_t gW3f[2 * 128];    // L3: ktp(2)
__device__ float    gB1s[64];         // b1/step (exact fractional)
__device__ float    gB2s[64];         // b2/step
__device__ float    gB3[8];           // b3 (cols 6,7 = 0)

// ---- helpers ----
#define CVT_BF16X2(res, vlo, vhi) \
    asm("cvt.rn.bf16x2.f32 %0, %1, %2;" : "=r"(res) : "f"(vhi), "f"(vlo))

#define MMA16816(Cv, Av, b0, b1)                                              \
    asm volatile(                                                             \
        "mma.sync.aligned.m16n8k16.row.col.f32.bf16.bf16.f32 "                \
        "{%0,%1,%2,%3}, {%4,%5,%6,%7}, {%8,%9}, {%0,%1,%2,%3};"               \
        : "+f"((Cv)[0]), "+f"((Cv)[1]), "+f"((Cv)[2]), "+f"((Cv)[3])          \
        : "r"((Av)[0]), "r"((Av)[1]), "r"((Av)[2]), "r"((Av)[3]),             \
          "r"(b0), "r"(b1))

__device__ __forceinline__ float quant_in(float v) {
    const float INV = QMAXF / ACT_SCALE;
    v = fminf(fmaxf(v, -ACT_SCALE), ACT_SCALE);
    float t = fmaf(v, INV, MAGIC);
    return __fadd_rn(t, -MAGIC);
}

// requant 2 accumulators -> packed int-valued bf16x2 (Round-5-proven path)
__device__ __forceinline__ uint32_t requant2(float c0, float c1, float G, float2 b) {
    float f0 = fmaf(c0, G, b.x);
    float f1 = fmaf(c1, G, b.y);
    f0 = fminf(fmaxf(f0, -QMAXF), QMAXF);
    f1 = fminf(fmaxf(f1, -QMAXF), QMAXF);
    f0 = __fadd_rn(__fadd_rn(f0, MAGIC), -MAGIC);
    f1 = __fadd_rn(__fadd_rn(f1, MAGIC), -MAGIC);
    uint32_t r; CVT_BF16X2(r, f0, f1);
    return r;
}

__device__ __forceinline__ uint16_t qweight(float w, float s) {
    float r = rintf(w / s);
    r = fminf(fmaxf(r, -QMAXF), QMAXF);
    return __bfloat16_as_ushort(__float2bfloat16(r));
}

// ============================================================================
// Prep: scales, quantize weights, bake into B-fragment order.
//   B reg b0 of tile (kt, nt), lane L: n = nt*8 + L/4, k0 = kt*16 + (L%4)*2,
//      b0 = bf16x2{ lo = W[n][k0], hi = W[n][k0+1] },  b1: k0+8.
// ============================================================================
__global__ void prep_kernel(const float* __restrict__ W1, const float* __restrict__ b1,
                            const float* __restrict__ W2, const float* __restrict__ b2,
                            const float* __restrict__ W3, const float* __restrict__ b3) {
    __shared__ float red[256];
    __shared__ float sS[3];
    const int tid = threadIdx.x;
    const float* Ws[3]  = {W1, W2, W3};
    const int    nel[3] = {64 * 17, 64 * 64, 6 * 64};

    for (int t = 0; t < 3; ++t) {
        float m = 0.0f;
        for (int i = tid; i < nel[t]; i += 256) m = fmaxf(m, fabsf(Ws[t][i]));
        red[tid] = m; __syncthreads();
        for (int s = 128; s > 0; s >>= 1) {
            if (tid < s) red[tid] = fmaxf(red[tid], red[tid + s]);
            __syncthreads();
        }
        if (tid == 0) sS[t] = red[0] / QMAXF;
        __syncthreads();
    }
    const float s1 = sS[0], s2 = sS[1], s3 = sS[2];
    const float step = ACT_SCALE / QMAXF;
    if (tid == 0) { gQ.G1 = s1; gQ.G2 = s2; gQ.G3 = step * s3; }
    if (tid < 64) {
        gB1s[tid] = b1[tid] / step;
        gB2s[tid] = b2[tid] / step;
    }
    if (tid < 8) gB3[tid] = (tid < 6) ? b3[tid] : 0.0f;

    // L1 frags: chunk c = kt*4 + ntp; j: nt = ntp*2 + j/2, jj = j%2
    for (int idx = tid; idx < 8 * 128; idx += 256) {
        int c = idx >> 7, rem = idx & 127;
        int lane = rem >> 2, j = rem & 3;
        int kt = c >> 2, ntp = c & 3;
        int nt = ntp * 2 + (j >> 1), jj = j & 1;
        int n  = nt * 8 + (lane >> 2);
        int k0 = kt * 16 + (lane & 3) * 2 + jj * 8;
        uint16_t lo = (k0     < 17) ? qweight(W1[n * 17 + k0],     s1) : (uint16_t)0;
        uint16_t hi = (k0 + 1 < 17) ? qweight(W1[n * 17 + k0 + 1], s1) : (uint16_t)0;
        gW1f[idx] = (uint32_t)lo | ((uint32_t)hi << 16);
    }
    // L2 frags
    for (int idx = tid; idx < 16 * 128; idx += 256) {
        int c = idx >> 7, rem = idx & 127;
        int lane = rem >> 2, j = rem & 3;
        int kt = c >> 2, ntp = c & 3;
        int nt = ntp * 2 + (j >> 1), jj = j & 1;
        int n  = nt * 8 + (lane >> 2);
        int k0 = kt * 16 + (lane & 3) * 2 + jj * 8;
        uint16_t lo = qweight(W2[(n << 6) + k0],     s2);
        uint16_t hi = qweight(W2[(n << 6) + k0 + 1], s2);
        gW2f[idx] = (uint32_t)lo | ((uint32_t)hi << 16);
    }
    // L3 frags: chunk c = ktp; j: kt = ktp*2 + j/2, jj = j%2, single N-tile
    for (int idx = tid; idx < 2 * 128; idx += 256) {
        int c = idx >> 7, rem = idx & 127;
        int lane = rem >> 2, j = rem & 3;
        int kt = c * 2 + (j >> 1), jj = j & 1;
        int n  = lane >> 2;
        int k0 = kt * 16 + (lane & 3) * 2 + jj * 8;
        uint16_t lo = (n < 6) ? qweight(W3[(n << 6) + k0],     s3) : (uint16_t)0;
        uint16_t hi = (n < 6) ? qweight(W3[(n << 6) + k0 + 1], s3) : (uint16_t)0;
        gW3f[idx] = (uint32_t)lo | ((uint32_t)hi << 16);
    }
}

// ============================================================================
// Main kernel: 256 threads = 8 warps; each warp owns TWO 16-row m-tiles
// (32 rows) -> 256 rows per CTA. Weight chunks feed 4 MMAs each.
// ============================================================================
__global__ __launch_bounds__(256, 2) void mlp_kernel(
    const float* __restrict__ x, float* __restrict__ out, int B) {

    __shared__ float    sx[256 * 18];          // padded stride 18
    __shared__ uint32_t sW1[8 * 128];
    __shared__ uint32_t sW2[16 * 128];
    __shared__ uint32_t sW3[2 * 128];
    __shared__ float    sb1[64], sb2[64], sb3[8];

    const int tid  = threadIdx.x;
    const int warp = tid >> 5;
    const int lane = tid & 31;
    const int g    = lane >> 2;   // row group 0..7
    const int t    = lane & 3;    // col/k group 0..3
    const int rowbase = blockIdx.x * 256;

    // ---- stage weights + biases + input tile ----
    for (int i = tid; i < 8 * 128;  i += 256) sW1[i] = gW1f[i];
    for (int i = tid; i < 16 * 128; i += 256) sW2[i] = gW2f[i];
    sW3[tid] = gW3f[tid];
    if (tid < 64) { sb1[tid] = gB1s[tid]; sb2[tid] = gB2s[tid]; }
    if (tid < 8)  sb3[tid] = gB3[tid];

    for (int i = tid; i < 256 * 17; i += 256) {
        int r = i / 17, k = i - r * 17;
        int gr = rowbase + r;
        sx[r * 18 + k] = (gr < B) ? x[(size_t)gr * 17 + k] : 0.0f;
    }
    __syncthreads();

    // local rows: tile u in {0,1}: r0 = warp*32 + u*16 + g, r1 = r0 + 8
    const int rbase = warp * 32 + g;

    // ---- input A fragments, both tiles (K = 32, cols >= 17 zero) ----
    uint32_t A1[2][2][4];
#pragma unroll
    for (int u = 0; u < 2; ++u) {
        const float* x0 = sx + (rbase + u * 16) * 18;
        const float* x1 = x0 + 8 * 18;
        float q00 = quant_in(x0[2 * t]),      q01 = quant_in(x0[2 * t + 1]);
        float q10 = quant_in(x1[2 * t]),      q11 = quant_in(x1[2 * t + 1]);
        float q02 = quant_in(x0[2 * t + 8]),  q03 = quant_in(x0[2 * t + 9]);
        float q12 = quant_in(x1[2 * t + 8]),  q13 = quant_in(x1[2 * t + 9]);
        CVT_BF16X2(A1[u][0][0], q00, q01);
        CVT_BF16X2(A1[u][0][1], q10, q11);
        CVT_BF16X2(A1[u][0][2], q02, q03);
        CVT_BF16X2(A1[u][0][3], q12, q13);
        if (t == 0) {
            float qa = quant_in(x0[16]);
            float qb = quant_in(x1[16]);
            CVT_BF16X2(A1[u][1][0], qa, 0.0f);
            CVT_BF16X2(A1[u][1][1], qb, 0.0f);
        } else {
            A1[u][1][0] = 0u; A1[u][1][1] = 0u;
        }
        A1[u][1][2] = 0u; A1[u][1][3] = 0u;
    }

    const float G1 = cQ.G1, G2 = cQ.G2, G3 = cQ.G3;
    const float2* sb1v = (const float2*)sb1;   // pair index nt*4 + t
    const float2* sb2v = (const float2*)sb2;

    // ---- layer 1: per N-pair p, all kt, requant immediately ----
    uint32_t A2[2][4][4];
#pragma unroll
    for (int p = 0; p < 4; ++p) {
        float C[2][2][4];
#pragma unroll
        for (int u = 0; u < 2; ++u)
#pragma unroll
            for (int q = 0; q < 2; ++q)
#pragma unroll
                for (int j = 0; j < 4; ++j) C[u][q][j] = 0.0f;
#pragma unroll
        for (int kt = 0; kt < 2; ++kt) {
            uint4 w = *(const uint4*)&sW1[((kt * 4 + p) << 7) + (lane << 2)];
#pragma unroll
            for (int u = 0; u < 2; ++u) {
                MMA16816(C[u][0], A1[u][kt], w.x, w.y);
                MMA16816(C[u][1], A1[u][kt], w.z, w.w);
            }
        }
        const float2 bA = sb1v[(2 * p) * 4 + t];
        const float2 bB = sb1v[(2 * p + 1) * 4 + t];
#pragma unroll
        for (int u = 0; u < 2; ++u) {
            A2[u][p][0] = requant2(C[u][0][0], C[u][0][1], G1, bA);
            A2[u][p][1] = requant2(C[u][0][2], C[u][0][3], G1, bA);
            A2[u][p][2] = requant2(C[u][1][0], C[u][1][1], G1, bB);
            A2[u][p][3] = requant2(C[u][1][2], C[u][1][3], G1, bB);
        }
    }

    // ---- layer 2: per N-pair p, kt 0..3, requant immediately ----
    uint32_t A3[2][4][4];
#pragma unroll
    for (int p = 0; p < 4; ++p) {
        float C[2][2][4];
#pragma unroll
        for (int u = 0; u < 2; ++u)
#pragma unroll
            for (int q = 0; q < 2; ++q)
#pragma unroll
                for (int j = 0; j < 4; ++j) C[u][q][j] = 0.0f;
#pragma unroll
        for (int kt = 0; kt < 4; ++kt) {
            uint4 w = *(const uint4*)&sW2[((kt * 4 + p) << 7) + (lane << 2)];
#pragma unroll
            for (int u = 0; u < 2; ++u) {
                MMA16816(C[u][0], A2[u][kt], w.x, w.y);
                MMA16816(C[u][1], A2[u][kt], w.z, w.w);
            }
        }
        const float2 bA = sb2v[(2 * p) * 4 + t];
        const float2 bB = sb2v[(2 * p + 1) * 4 + t];
#pragma unroll
        for (int u = 0; u < 2; ++u) {
            A3[u][p][0] = requant2(C[u][0][0], C[u][0][1], G2, bA);
            A3[u][p][1] = requant2(C[u][0][2], C[u][0][3], G2, bA);
            A3[u][p][2] = requant2(C[u][1][0], C[u][1][1], G2, bB);
            A3[u][p][3] = requant2(C[u][1][2], C[u][1][3], G2, bB);
        }
    }

    // ---- layer 3: single N-tile, kt 0..3, both M-tiles ----
    float D[2][4];
#pragma unroll
    for (int u = 0; u < 2; ++u)
#pragma unroll
        for (int j = 0; j < 4; ++j) D[u][j] = 0.0f;
#pragma unroll
    for (int p = 0; p < 2; ++p) {
        uint4 w = *(const uint4*)&sW3[(p << 7) + (lane << 2)];
#pragma unroll
        for (int u = 0; u < 2; ++u) {
            MMA16816(D[u], A3[u][2 * p],     w.x, w.y);
            MMA16816(D[u], A3[u][2 * p + 1], w.z, w.w);
        }
    }

    // ---- epilogue: out[row, 2t..2t+1] (t < 3) ----
    if (t < 3) {
        const float2 b3p = *(const float2*)&sb3[2 * t];
#pragma unroll
        for (int u = 0; u < 2; ++u) {
            const int gr0 = rowbase + rbase + u * 16;
            const int gr1 = gr0 + 8;
            if (gr0 < B) {
                float2 o;
                o.x = fmaf(D[u][0], G3, b3p.x);
                o.y = fmaf(D[u][1], G3, b3p.y);
                *(float2*)&out[(size_t)gr0 * 6 + 2 * t] = o;
            }
            if (gr1 < B) {
                float2 o;
                o.x = fmaf(D[u][2], G3, b3p.x);
                o.y = fmaf(D[u][3], G3, b3p.y);
                *(float2*)&out[(size_t)gr1 * 6 + 2 * t] = o;
            }
        }
    }
}

extern "C" void kernel_launch(void* const* d_in, const int* in_sizes, int n_in,
                              void* d_out, int out_size) {
    const float* x  = (const float*)d_in[0];
    const float* W1 = (const float*)d_in[1];
    const float* b1 = (const float*)d_in[2];
    const float* W2 = (const float*)d_in[3];
    const float* b2 = (const float*)d_in[4];
    const float* W3 = (const float*)d_in[5];
    const float* b3 = (const float*)d_in[6];
    float* out = (float*)d_out;

    const int B = in_sizes[0] / 17;
    const int blocks = (B + 255) / 256;

    prep_kernel<<<1, 256>>>(W1, b1, W2, b2, W3, b3);

    void* gq_ptr = nullptr;
    cudaGetSymbolAddress(&gq_ptr, gQ);
    cudaMemcpyToSymbolAsync(cQ, gq_ptr, sizeof(QConst), 0,
                            cudaMemcpyDeviceToDevice, 0);

    mlp_kernel<<<blocks, 256>>>(x, out, B);
}